// round 2
// baseline (speedup 1.0000x reference)
#include <cuda_runtime.h>
#include <cstdint>

#define HW   (1024 * 1024)
#define NB   4
#define NC   3
#define MH   25
#define NDEPTH 6
#define CPAD 26           // padded inner dim (25 -> 26) so rows are 13 x ulonglong2
#define Q13  13

typedef unsigned long long u64;

// ---------- packed f32x2 helpers ----------
__device__ __forceinline__ u64 pack2(float lo, float hi) {
    u64 r; asm("mov.b64 %0, {%1, %2};" : "=l"(r) : "f"(lo), "f"(hi)); return r;
}
__device__ __forceinline__ void unpack2(u64 v, float& lo, float& hi) {
    asm("mov.b64 {%0, %1}, %2;" : "=f"(lo), "=f"(hi) : "l"(v));
}
__device__ __forceinline__ u64 fma2_(u64 a, u64 b, u64 c) {
    u64 d; asm("fma.rn.f32x2 %0, %1, %2, %3;" : "=l"(d) : "l"(a), "l"(b), "l"(c)); return d;
}
__device__ __forceinline__ u64 mul2_(u64 a, u64 b) {
    u64 d; asm("mul.rn.f32x2 %0, %1, %2;" : "=l"(d) : "l"(a), "l"(b)); return d;
}

// Packed tanh constants (alphas NEGATED: the magic-recip chain yields -1/q,
// so (-p) * (-1/q) = tanh with zero extra sign ops).
struct TanhC {
    u64 na1, na3, na5, na7, na9, na11, na13;
    u64 b0, b2, b4, b6;
    u64 m2, p2;
    float clampv;
};

__device__ __forceinline__ u64 cpair(float c) {
    unsigned b = __float_as_uint(c);
    return ((u64)b << 32) | (u64)b;
}

// MUFU-free packed tanh: Eigen-style rational x*P6(x2)/Q3(x2), clamp |x|<=7.9053,
// reciprocal via magic bit-hack (ALU pipe) + 2 packed Newton iterations.
__device__ __forceinline__ u64 tanh2(u64 v, const TanhC& K) {
    float lo, hi;
    unpack2(v, lo, hi);
    lo = fminf(fmaxf(lo, -K.clampv), K.clampv);   // FMNMX -> ALU pipe
    hi = fminf(fmaxf(hi, -K.clampv), K.clampv);
    v = pack2(lo, hi);

    u64 x2 = mul2_(v, v);

    u64 p = K.na13;
    p = fma2_(p, x2, K.na11);
    p = fma2_(p, x2, K.na9);
    p = fma2_(p, x2, K.na7);
    p = fma2_(p, x2, K.na5);
    p = fma2_(p, x2, K.na3);
    p = fma2_(p, x2, K.na1);
    p = mul2_(p, v);                              // p = -x * P(x2)

    u64 q = K.b6;
    q = fma2_(q, x2, K.b4);
    q = fma2_(q, x2, K.b2);
    q = fma2_(q, x2, K.b0);                       // q > 0 always

    // fast reciprocal guess per half (IADD -> ALU pipe), then packed Newton
    unsigned qlo = (unsigned)q, qhi = (unsigned)(q >> 32);
    unsigned rl = 0x7EF311C3u - qlo;
    unsigned rh = 0x7EF311C3u - qhi;
    u64 r = ((u64)rh << 32) | (u64)rl;            // r ~= +1/q (±~5%)
    u64 e = fma2_(q, r, K.m2);                    // q*r - 2
    r = mul2_(r, e);                              // -> -r(2-qr)  (negative)
    e = fma2_(q, r, K.p2);                        // 2 - q*|r|
    r = mul2_(r, e);                              // -> ~ -1/q

    return mul2_(p, r);                           // (-p)*(-1/q) = tanh(x)
}

__device__ __forceinline__ float sigm(float z) {
    float e = __expf(-z);                         // MUFU.EX2 (cheap: 3/pixel)
    return __fdividef(1.0f, 1.0f + e);            // MUFU.RCP
}

__global__ __launch_bounds__(256)
void simplenet_kernel(const float* __restrict__ x,
                      const float* __restrict__ w_in,
                      const float* __restrict__ ws,
                      const float* __restrict__ w_out,
                      float* __restrict__ out) {
    // Weights staged in SMEM pre-duplicated as {w,w} ull pairs so one LDS.128
    // (ulonglong2) delivers two ready f32x2 multiplicands.
    __shared__ __align__(16) u64 s_mid[NDEPTH][MH][CPAD];
    __shared__ __align__(16) u64 s_in[MH][NC];
    __shared__ __align__(16) u64 s_out[NC][CPAD];

    const int tid = threadIdx.x;

    for (int i = tid; i < NDEPTH * MH * CPAD; i += 256) {
        int l = i / (MH * CPAD);
        int rr = i - l * (MH * CPAD);
        int o = rr / CPAD;
        int c = rr - o * CPAD;
        float w = (c < MH) ? ws[(l * MH + o) * MH + c] : 0.0f;
        s_mid[l][o][c] = pack2(w, w);
    }
    for (int i = tid; i < MH * NC; i += 256) {
        float w = w_in[i];
        s_in[i / NC][i % NC] = pack2(w, w);
    }
    for (int i = tid; i < NC * CPAD; i += 256) {
        int o = i / CPAD, c = i - o * CPAD;
        float w = (c < MH) ? w_out[o * MH + c] : 0.0f;
        s_out[o][c] = pack2(w, w);
    }
    __syncthreads();

    TanhC K;
    K.na1  = cpair(-4.89352455891786e-03f);
    K.na3  = cpair(-6.37261928875436e-04f);
    K.na5  = cpair(-1.48572235717979e-05f);
    K.na7  = cpair(-5.12229709037114e-08f);
    K.na9  = cpair( 8.60467152213735e-11f);
    K.na11 = cpair(-2.00018790482477e-13f);
    K.na13 = cpair( 2.76076847742355e-16f);
    K.b0   = cpair(4.89352518554385e-03f);
    K.b2   = cpair(2.26843463243900e-03f);
    K.b4   = cpair(1.18534705686654e-04f);
    K.b6   = cpair(1.19825839466702e-06f);
    K.m2   = cpair(-2.0f);
    K.p2   = cpair( 2.0f);
    K.clampv = 7.90531110763549805f;

    unsigned gp  = blockIdx.x * 256u + (unsigned)tid;   // pixel-pair index
    unsigned idx = gp * 2u;
    if (idx >= (unsigned)(NB * HW)) return;
    unsigned b   = idx >> 20;                 // / HW
    unsigned rem = idx & (HW - 1);

    const float* px = x + (size_t)b * (NC * HW) + rem;
    float2 v0 = *(const float2*)(px);
    float2 v1 = *(const float2*)(px + HW);
    float2 v2 = *(const float2*)(px + 2 * HW);
    u64 xin0 = pack2(v0.x, v0.y);
    u64 xin1 = pack2(v1.x, v1.y);
    u64 xin2 = pack2(v2.x, v2.y);

    u64 h[CPAD];
    u64 acc[MH];
    h[MH] = 0ull;                             // zero pad lane (pairs with c=25 pad weight)

    // ---- input layer: 3 -> 25, tanh ----
#pragma unroll
    for (int o = 0; o < MH; o++) {
        u64 a = mul2_(s_in[o][0], xin0);
        a = fma2_(s_in[o][1], xin1, a);
        a = fma2_(s_in[o][2], xin2, a);
        h[o] = tanh2(a, K);
    }

    // ---- 6 hidden layers: 25 -> 25, tanh ----
#pragma unroll 1
    for (int l = 0; l < NDEPTH; l++) {
        const ulonglong2* wl = (const ulonglong2*)&s_mid[l][0][0];
#pragma unroll
        for (int o = 0; o < MH; o++) {
            const ulonglong2* wr = wl + o * Q13;
            ulonglong2 w = wr[0];
            u64 a = mul2_(w.x, h[0]);
            a = fma2_(w.y, h[1], a);
#pragma unroll
            for (int qq = 1; qq < Q13; qq++) {
                w = wr[qq];
                a = fma2_(w.x, h[2 * qq], a);
                a = fma2_(w.y, h[2 * qq + 1], a);
            }
            acc[o] = a;
        }
#pragma unroll
        for (int o = 0; o < MH; o++) h[o] = tanh2(acc[o], K);
    }

    // ---- output layer: 25 -> 3, sigmoid ----
    float* po = out + (size_t)b * (NC * HW) + rem;
#pragma unroll
    for (int o = 0; o < NC; o++) {
        const ulonglong2* wr = (const ulonglong2*)&s_out[o][0];
        ulonglong2 w = wr[0];
        u64 a = mul2_(w.x, h[0]);
        a = fma2_(w.y, h[1], a);
#pragma unroll
        for (int qq = 1; qq < Q13; qq++) {
            w = wr[qq];
            a = fma2_(w.x, h[2 * qq], a);
            a = fma2_(w.y, h[2 * qq + 1], a);
        }
        float zl, zh;
        unpack2(a, zl, zh);
        *(float2*)(po + o * HW) = make_float2(sigm(zl), sigm(zh));
    }
}

extern "C" void kernel_launch(void* const* d_in, const int* in_sizes, int n_in,
                              void* d_out, int out_size) {
    const float* x     = (const float*)d_in[0];
    const float* w_in  = (const float*)d_in[1];
    const float* ws    = (const float*)d_in[2];
    const float* w_out = (const float*)d_in[3];
    float* out = (float*)d_out;

    const int pairs = NB * HW / 2;            // 2,097,152
    dim3 block(256);
    dim3 grid(pairs / 256);                   // 8192
    simplenet_kernel<<<grid, block>>>(x, w_in, ws, w_out, out);
}

// round 3
// speedup vs baseline: 1.0604x; 1.0604x over previous
#include <cuda_runtime.h>
#include <cstdint>

#define HW   (1024 * 1024)
#define NB   4
#define NC   3
#define MH   25
#define NDEPTH 6
#define NOP  13           // neuron-pair count (25 outputs -> 13 pairs, last has pad)
#define NOPP 14           // padded to 14 for 16B-aligned rows

typedef unsigned long long u64;

// ---------- packed f32x2 helpers ----------
__device__ __forceinline__ u64 pack2(float lo, float hi) {
    u64 r; asm("mov.b64 %0, {%1, %2};" : "=l"(r) : "f"(lo), "f"(hi)); return r;
}
__device__ __forceinline__ void unpack2(u64 v, float& lo, float& hi) {
    asm("mov.b64 {%0, %1}, %2;" : "=f"(lo), "=f"(hi) : "l"(v));
}
__device__ __forceinline__ u64 fma2_(u64 a, u64 b, u64 c) {
    u64 d; asm("fma.rn.f32x2 %0, %1, %2, %3;" : "=l"(d) : "l"(a), "l"(b), "l"(c)); return d;
}
__device__ __forceinline__ u64 mul2_(u64 a, u64 b) {
    u64 d; asm("mul.rn.f32x2 %0, %1, %2;" : "=l"(d) : "l"(a), "l"(b)); return d;
}

// Packed tanh constants (alphas NEGATED: the magic-recip chain yields -1/q,
// so (-p) * (-1/q) = tanh with zero extra sign ops).
struct TanhC {
    u64 na1, na3, na5, na7, na9, na11, na13;
    u64 b0, b2, b4, b6;
    u64 m2, p2;
    float clampv;
};

__device__ __forceinline__ u64 cpair(float c) {
    unsigned b = __float_as_uint(c);
    return ((u64)b << 32) | (u64)b;
}

// MUFU-free packed tanh: Eigen-style rational x*P6(x2)/Q3(x2), clamp |x|<=7.9053,
// reciprocal via magic bit-hack (ALU pipe) + 2 packed Newton iterations.
__device__ __forceinline__ u64 tanh2(u64 v, const TanhC& K) {
    float lo, hi;
    unpack2(v, lo, hi);
    lo = fminf(fmaxf(lo, -K.clampv), K.clampv);   // FMNMX -> ALU pipe
    hi = fminf(fmaxf(hi, -K.clampv), K.clampv);
    v = pack2(lo, hi);

    u64 x2 = mul2_(v, v);

    u64 p = K.na13;
    p = fma2_(p, x2, K.na11);
    p = fma2_(p, x2, K.na9);
    p = fma2_(p, x2, K.na7);
    p = fma2_(p, x2, K.na5);
    p = fma2_(p, x2, K.na3);
    p = fma2_(p, x2, K.na1);
    p = mul2_(p, v);                              // p = -x * P(x2)

    u64 q = K.b6;
    q = fma2_(q, x2, K.b4);
    q = fma2_(q, x2, K.b2);
    q = fma2_(q, x2, K.b0);                       // q > 0 always

    // fast reciprocal guess per half (IADD -> ALU pipe), then packed Newton
    unsigned qlo = (unsigned)q, qhi = (unsigned)(q >> 32);
    unsigned rl = 0x7EF311C3u - qlo;
    unsigned rh = 0x7EF311C3u - qhi;
    u64 r = ((u64)rh << 32) | (u64)rl;            // r ~= +1/q (±~5%)
    u64 e = fma2_(q, r, K.m2);                    // q*r - 2
    r = mul2_(r, e);                              // -> -r(2-qr)  (negative)
    e = fma2_(q, r, K.p2);                        // 2 - q*|r|
    r = mul2_(r, e);                              // -> ~ -1/q

    return mul2_(p, r);                           // (-p)*(-1/q) = tanh(x)
}

__device__ __forceinline__ float sigm(float z) {
    float e = __expf(-z);                         // MUFU.EX2 (cheap: 3/pixel)
    return __fdividef(1.0f, 1.0f + e);            // MUFU.RCP
}

__global__ __launch_bounds__(128)
void simplenet_kernel(const float* __restrict__ x,
                      const float* __restrict__ w_in,
                      const float* __restrict__ ws,
                      const float* __restrict__ w_out,
                      float* __restrict__ out) {
    // Weight layout: neuron-pair packing {w[2op][c], w[2op+1][c]} per u64.
    // No duplication -> half the LDS bytes of the {w,w} scheme.
    __shared__ __align__(16) u64   s_mid[NDEPTH][MH][NOPP];  // [layer][c][op]
    __shared__ __align__(16) u64   s_in[NC][NOPP];           // [c][op]
    __shared__ __align__(16) float s_wout[NOP][8];           // [i][o*2+half]

    const int tid = threadIdx.x;

    for (int t = tid; t < NDEPTH * MH * NOPP; t += 128) {
        int l  = t / (MH * NOPP);
        int r  = t - l * (MH * NOPP);
        int c  = r / NOPP;
        int op = r - c * NOPP;
        int o0 = 2 * op, o1 = 2 * op + 1;
        float lo = (o0 < MH) ? ws[(l * MH + o0) * MH + c] : 0.0f;
        float hi = (o1 < MH) ? ws[(l * MH + o1) * MH + c] : 0.0f;
        s_mid[l][c][op] = pack2(lo, hi);
    }
    for (int t = tid; t < NC * NOPP; t += 128) {
        int c = t / NOPP, op = t - (t / NOPP) * NOPP;
        int o0 = 2 * op, o1 = 2 * op + 1;
        float lo = (o0 < MH) ? w_in[o0 * NC + c] : 0.0f;
        float hi = (o1 < MH) ? w_in[o1 * NC + c] : 0.0f;
        s_in[c][op] = pack2(lo, hi);
    }
    for (int t = tid; t < NOP * 8; t += 128) {
        int i = t / 8, j = t - (t / 8) * 8;
        int o = j >> 1, half = j & 1;
        int c = 2 * i + half;
        s_wout[i][j] = (o < NC && c < MH) ? w_out[o * MH + c] : 0.0f;
    }
    __syncthreads();

    TanhC K;
    K.na1  = cpair(-4.89352455891786e-03f);
    K.na3  = cpair(-6.37261928875436e-04f);
    K.na5  = cpair(-1.48572235717979e-05f);
    K.na7  = cpair(-5.12229709037114e-08f);
    K.na9  = cpair( 8.60467152213735e-11f);
    K.na11 = cpair(-2.00018790482477e-13f);
    K.na13 = cpair( 2.76076847742355e-16f);
    K.b0   = cpair(4.89352518554385e-03f);
    K.b2   = cpair(2.26843463243900e-03f);
    K.b4   = cpair(1.18534705686654e-04f);
    K.b6   = cpair(1.19825839466702e-06f);
    K.m2   = cpair(-2.0f);
    K.p2   = cpair( 2.0f);
    K.clampv = 7.90531110763549805f;

    unsigned gp  = blockIdx.x * 128u + (unsigned)tid;   // pixel-pair index
    unsigned idx = gp * 2u;
    if (idx >= (unsigned)(NB * HW)) return;
    unsigned b   = idx >> 20;                 // / HW
    unsigned rem = idx & (HW - 1);

    const float* px = x + (size_t)b * (NC * HW) + rem;
    float2 v0 = *(const float2*)(px);                 // (pixA, pixB) channel 0
    float2 v1 = *(const float2*)(px + HW);
    float2 v2 = *(const float2*)(px + 2 * HW);

    // Per-pixel state: 13 neuron-pair accumulators each.
    u64 hA[NOP], hB[NOP];
    u64 aA[NOP], aB[NOP];

    // ---- input layer: 3 -> 25 (neuron-pair packed), tanh ----
    {
        u64 dA = pack2(v0.x, v0.x), dB = pack2(v0.y, v0.y);
#pragma unroll
        for (int op = 0; op < NOP; op++) {
            u64 w = s_in[0][op];
            aA[op] = mul2_(w, dA);
            aB[op] = mul2_(w, dB);
        }
        dA = pack2(v1.x, v1.x); dB = pack2(v1.y, v1.y);
#pragma unroll
        for (int op = 0; op < NOP; op++) {
            u64 w = s_in[1][op];
            aA[op] = fma2_(w, dA, aA[op]);
            aB[op] = fma2_(w, dB, aB[op]);
        }
        dA = pack2(v2.x, v2.x); dB = pack2(v2.y, v2.y);
#pragma unroll
        for (int op = 0; op < NOP; op++) {
            u64 w = s_in[2][op];
            aA[op] = fma2_(w, dA, aA[op]);
            aB[op] = fma2_(w, dB, aB[op]);
        }
#pragma unroll
        for (int op = 0; op < NOP; op++) {
            hA[op] = tanh2(aA[op], K);
            hB[op] = tanh2(aB[op], K);
        }
    }

    // ---- 6 hidden layers: 25 -> 25, tanh ----
#pragma unroll 1
    for (int l = 0; l < NDEPTH; l++) {
        const u64* wl = &s_mid[l][0][0];
#pragma unroll
        for (int i = 0; i < NOP; i++) {           // i indexes h pair (c = 2i, 2i+1)
            float a0, a1, b0, b1;
            unpack2(hA[i], a0, a1);
            unpack2(hB[i], b0, b1);
            {
                u64 dA = pack2(a0, a0), dB = pack2(b0, b0);
                const u64* wr = wl + (2 * i) * NOPP;
#pragma unroll
                for (int op = 0; op < NOP; op++) {
                    u64 w = wr[op];
                    if (i == 0) {
                        aA[op] = mul2_(w, dA);
                        aB[op] = mul2_(w, dB);
                    } else {
                        aA[op] = fma2_(w, dA, aA[op]);
                        aB[op] = fma2_(w, dB, aB[op]);
                    }
                }
            }
            if (2 * i + 1 < MH) {                 // skip pad lane c=25
                u64 dA = pack2(a1, a1), dB = pack2(b1, b1);
                const u64* wr = wl + (2 * i + 1) * NOPP;
#pragma unroll
                for (int op = 0; op < NOP; op++) {
                    u64 w = wr[op];
                    aA[op] = fma2_(w, dA, aA[op]);
                    aB[op] = fma2_(w, dB, aB[op]);
                }
            }
        }
#pragma unroll
        for (int op = 0; op < NOP; op++) {
            hA[op] = tanh2(aA[op], K);            // pad lane: weights 0 -> tanh(0)=0
            hB[op] = tanh2(aB[op], K);
        }
    }

    // ---- output layer: 25 -> 3, scalar (components are free register halves) ----
    float zA0 = 0.f, zA1 = 0.f, zA2 = 0.f;
    float zB0 = 0.f, zB1 = 0.f, zB2 = 0.f;
#pragma unroll
    for (int i = 0; i < NOP; i++) {
        float a0, a1, b0, b1;
        unpack2(hA[i], a0, a1);
        unpack2(hB[i], b0, b1);
        float w00 = s_wout[i][0], w01 = s_wout[i][1];
        float w10 = s_wout[i][2], w11 = s_wout[i][3];
        float w20 = s_wout[i][4], w21 = s_wout[i][5];
        zA0 = fmaf(w00, a0, fmaf(w01, a1, zA0));
        zA1 = fmaf(w10, a0, fmaf(w11, a1, zA1));
        zA2 = fmaf(w20, a0, fmaf(w21, a1, zA2));
        zB0 = fmaf(w00, b0, fmaf(w01, b1, zB0));
        zB1 = fmaf(w10, b0, fmaf(w11, b1, zB1));
        zB2 = fmaf(w20, b0, fmaf(w21, b1, zB2));
    }

    float* po = out + (size_t)b * (NC * HW) + rem;
    *(float2*)(po)          = make_float2(sigm(zA0), sigm(zB0));
    *(float2*)(po + HW)     = make_float2(sigm(zA1), sigm(zB1));
    *(float2*)(po + 2 * HW) = make_float2(sigm(zA2), sigm(zB2));
}

extern "C" void kernel_launch(void* const* d_in, const int* in_sizes, int n_in,
                              void* d_out, int out_size) {
    const float* x     = (const float*)d_in[0];
    const float* w_in  = (const float*)d_in[1];
    const float* ws    = (const float*)d_in[2];
    const float* w_out = (const float*)d_in[3];
    float* out = (float*)d_out;

    const int pairs = NB * HW / 2;            // 2,097,152
    dim3 block(128);
    dim3 grid(pairs / 128);                   // 16384
    simplenet_kernel<<<grid, block>>>(x, w_in, ws, w_out, out);
}

// round 4
// speedup vs baseline: 1.0621x; 1.0016x over previous
#include <cuda_runtime.h>
#include <cstdint>

#define HW   (1024 * 1024)
#define NB   4
#define NC   3
#define MH   25
#define NDEPTH 6
#define NOP  13           // neuron-pair count (25 outputs -> 13 pairs, last has pad)
#define NOPP 14           // padded to 14 for 16B-aligned rows

typedef unsigned long long u64;

// ---------- packed f32x2 helpers ----------
__device__ __forceinline__ u64 pack2(float lo, float hi) {
    u64 r; asm("mov.b64 %0, {%1, %2};" : "=l"(r) : "f"(lo), "f"(hi)); return r;
}
__device__ __forceinline__ void unpack2(u64 v, float& lo, float& hi) {
    asm("mov.b64 {%0, %1}, %2;" : "=f"(lo), "=f"(hi) : "l"(v));
}
__device__ __forceinline__ u64 fma2_(u64 a, u64 b, u64 c) {
    u64 d; asm("fma.rn.f32x2 %0, %1, %2, %3;" : "=l"(d) : "l"(a), "l"(b), "l"(c)); return d;
}
__device__ __forceinline__ u64 mul2_(u64 a, u64 b) {
    u64 d; asm("mul.rn.f32x2 %0, %1, %2;" : "=l"(d) : "l"(a), "l"(b)); return d;
}

// Packed tanh constants (alphas NEGATED: the magic-recip chain yields -1/q,
// so (-p) * (-1/q) = tanh with zero extra sign ops).
struct TanhC {
    u64 na1, na3, na5, na7, na9, na11, na13;
    u64 b0, b2, b4, b6;
    u64 m2, p2;
    float clampv;
};

__device__ __forceinline__ u64 cpair(float c) {
    unsigned b = __float_as_uint(c);
    return ((u64)b << 32) | (u64)b;
}

// MUFU-free packed tanh: Eigen-style rational x*P6(x2)/Q3(x2), clamp |x|<=7.9053,
// reciprocal via magic bit-hack (ALU pipe) + 2 packed Newton iterations.
__device__ __forceinline__ u64 tanh2(u64 v, const TanhC& K) {
    float lo, hi;
    unpack2(v, lo, hi);
    lo = fminf(fmaxf(lo, -K.clampv), K.clampv);   // FMNMX -> ALU pipe
    hi = fminf(fmaxf(hi, -K.clampv), K.clampv);
    v = pack2(lo, hi);

    u64 x2 = mul2_(v, v);

    u64 p = K.na13;
    p = fma2_(p, x2, K.na11);
    p = fma2_(p, x2, K.na9);
    p = fma2_(p, x2, K.na7);
    p = fma2_(p, x2, K.na5);
    p = fma2_(p, x2, K.na3);
    p = fma2_(p, x2, K.na1);
    p = mul2_(p, v);                              // p = -x * P(x2)

    u64 q = K.b6;
    q = fma2_(q, x2, K.b4);
    q = fma2_(q, x2, K.b2);
    q = fma2_(q, x2, K.b0);                       // q > 0 always

    // fast reciprocal guess per half (IADD -> ALU pipe), then packed Newton
    unsigned qlo = (unsigned)q, qhi = (unsigned)(q >> 32);
    unsigned rl = 0x7EF311C3u - qlo;
    unsigned rh = 0x7EF311C3u - qhi;
    u64 r = ((u64)rh << 32) | (u64)rl;            // r ~= +1/q (±~5%)
    u64 e = fma2_(q, r, K.m2);                    // q*r - 2
    r = mul2_(r, e);                              // -> -r(2-qr)  (negative)
    e = fma2_(q, r, K.p2);                        // 2 - q*|r|
    r = mul2_(r, e);                              // -> ~ -1/q

    return mul2_(p, r);                           // (-p)*(-1/q) = tanh(x)
}

__device__ __forceinline__ float sigm(float z) {
    float e = __expf(-z);                         // MUFU.EX2 (cheap: 3/pixel)
    return __fdividef(1.0f, 1.0f + e);            // MUFU.RCP
}

__global__ __launch_bounds__(128, 4)
void simplenet_kernel(const float* __restrict__ x,
                      const float* __restrict__ w_in,
                      const float* __restrict__ ws,
                      const float* __restrict__ w_out,
                      float* __restrict__ out) {
    // Weight layout: neuron-pair packing {w[2op][c], w[2op+1][c]} per u64.
    // No duplication -> half the LDS bytes of the {w,w} scheme.
    __shared__ __align__(16) u64   s_mid[NDEPTH][MH][NOPP];  // [layer][c][op]
    __shared__ __align__(16) u64   s_in[NC][NOPP];           // [c][op]
    __shared__ __align__(16) float s_wout[NOP][8];           // [i][o*2+half]

    const int tid = threadIdx.x;

    for (int t = tid; t < NDEPTH * MH * NOPP; t += 128) {
        int l  = t / (MH * NOPP);
        int r  = t - l * (MH * NOPP);
        int c  = r / NOPP;
        int op = r - c * NOPP;
        int o0 = 2 * op, o1 = 2 * op + 1;
        float lo = (o0 < MH) ? ws[(l * MH + o0) * MH + c] : 0.0f;
        float hi = (o1 < MH) ? ws[(l * MH + o1) * MH + c] : 0.0f;
        s_mid[l][c][op] = pack2(lo, hi);
    }
    for (int t = tid; t < NC * NOPP; t += 128) {
        int c = t / NOPP, op = t - (t / NOPP) * NOPP;
        int o0 = 2 * op, o1 = 2 * op + 1;
        float lo = (o0 < MH) ? w_in[o0 * NC + c] : 0.0f;
        float hi = (o1 < MH) ? w_in[o1 * NC + c] : 0.0f;
        s_in[c][op] = pack2(lo, hi);
    }
    for (int t = tid; t < NOP * 8; t += 128) {
        int i = t / 8, j = t - (t / 8) * 8;
        int o = j >> 1, half = j & 1;
        int c = 2 * i + half;
        s_wout[i][j] = (o < NC && c < MH) ? w_out[o * MH + c] : 0.0f;
    }
    __syncthreads();

    TanhC K;
    K.na1  = cpair(-4.89352455891786e-03f);
    K.na3  = cpair(-6.37261928875436e-04f);
    K.na5  = cpair(-1.48572235717979e-05f);
    K.na7  = cpair(-5.12229709037114e-08f);
    K.na9  = cpair( 8.60467152213735e-11f);
    K.na11 = cpair(-2.00018790482477e-13f);
    K.na13 = cpair( 2.76076847742355e-16f);
    K.b0   = cpair(4.89352518554385e-03f);
    K.b2   = cpair(2.26843463243900e-03f);
    K.b4   = cpair(1.18534705686654e-04f);
    K.b6   = cpair(1.19825839466702e-06f);
    K.m2   = cpair(-2.0f);
    K.p2   = cpair( 2.0f);
    K.clampv = 7.90531110763549805f;

    unsigned gp  = blockIdx.x * 128u + (unsigned)tid;   // pixel-pair index
    unsigned idx = gp * 2u;                             // grid covers domain exactly
    unsigned b   = idx >> 20;                 // / HW
    unsigned rem = idx & (HW - 1);

    const float* px = x + (size_t)b * (NC * HW) + rem;
    float2 v0 = *(const float2*)(px);                 // (pixA, pixB) channel 0
    float2 v1 = *(const float2*)(px + HW);
    float2 v2 = *(const float2*)(px + 2 * HW);

    // Per-pixel state: 13 neuron-pair accumulators each.
    u64 hA[NOP], hB[NOP];
    u64 aA[NOP], aB[NOP];

    // ---- input layer: 3 -> 25 (neuron-pair packed), tanh ----
    {
        u64 dA = pack2(v0.x, v0.x), dB = pack2(v0.y, v0.y);
#pragma unroll
        for (int op = 0; op < NOP; op++) {
            u64 w = s_in[0][op];
            aA[op] = mul2_(w, dA);
            aB[op] = mul2_(w, dB);
        }
        dA = pack2(v1.x, v1.x); dB = pack2(v1.y, v1.y);
#pragma unroll
        for (int op = 0; op < NOP; op++) {
            u64 w = s_in[1][op];
            aA[op] = fma2_(w, dA, aA[op]);
            aB[op] = fma2_(w, dB, aB[op]);
        }
        dA = pack2(v2.x, v2.x); dB = pack2(v2.y, v2.y);
#pragma unroll
        for (int op = 0; op < NOP; op++) {
            u64 w = s_in[2][op];
            aA[op] = fma2_(w, dA, aA[op]);
            aB[op] = fma2_(w, dB, aB[op]);
        }
#pragma unroll
        for (int op = 0; op < NOP; op++) {
            hA[op] = tanh2(aA[op], K);
            hB[op] = tanh2(aB[op], K);
        }
    }

    // ---- 6 hidden layers: 25 -> 25, tanh ----
#pragma unroll 1
    for (int l = 0; l < NDEPTH; l++) {
        const u64* wl = &s_mid[l][0][0];
#pragma unroll
        for (int i = 0; i < NOP; i++) {           // i indexes h pair (c = 2i, 2i+1)
            float a0, a1, b0, b1;
            unpack2(hA[i], a0, a1);
            unpack2(hB[i], b0, b1);
            {
                u64 dA = pack2(a0, a0), dB = pack2(b0, b0);
                const u64* wr = wl + (2 * i) * NOPP;
#pragma unroll
                for (int op = 0; op < NOP; op++) {
                    u64 w = wr[op];
                    if (i == 0) {
                        aA[op] = mul2_(w, dA);
                        aB[op] = mul2_(w, dB);
                    } else {
                        aA[op] = fma2_(w, dA, aA[op]);
                        aB[op] = fma2_(w, dB, aB[op]);
                    }
                }
            }
            if (2 * i + 1 < MH) {                 // skip pad lane c=25
                u64 dA = pack2(a1, a1), dB = pack2(b1, b1);
                const u64* wr = wl + (2 * i + 1) * NOPP;
#pragma unroll
                for (int op = 0; op < NOP; op++) {
                    u64 w = wr[op];
                    aA[op] = fma2_(w, dA, aA[op]);
                    aB[op] = fma2_(w, dB, aB[op]);
                }
            }
        }
#pragma unroll
        for (int op = 0; op < NOP; op++) {
            hA[op] = tanh2(aA[op], K);            // pad lane: weights 0 -> tanh(0)=0
            hB[op] = tanh2(aB[op], K);
        }
    }

    // ---- output layer: 25 -> 3, scalar (components are free register halves) ----
    float zA0 = 0.f, zA1 = 0.f, zA2 = 0.f;
    float zB0 = 0.f, zB1 = 0.f, zB2 = 0.f;
#pragma unroll
    for (int i = 0; i < NOP; i++) {
        float a0, a1, b0, b1;
        unpack2(hA[i], a0, a1);
        unpack2(hB[i], b0, b1);
        float w00 = s_wout[i][0], w01 = s_wout[i][1];
        float w10 = s_wout[i][2], w11 = s_wout[i][3];
        float w20 = s_wout[i][4], w21 = s_wout[i][5];
        zA0 = fmaf(w00, a0, fmaf(w01, a1, zA0));
        zA1 = fmaf(w10, a0, fmaf(w11, a1, zA1));
        zA2 = fmaf(w20, a0, fmaf(w21, a1, zA2));
        zB0 = fmaf(w00, b0, fmaf(w01, b1, zB0));
        zB1 = fmaf(w10, b0, fmaf(w11, b1, zB1));
        zB2 = fmaf(w20, b0, fmaf(w21, b1, zB2));
    }

    float* po = out + (size_t)b * (NC * HW) + rem;
    *(float2*)(po)          = make_float2(sigm(zA0), sigm(zB0));
    *(float2*)(po + HW)     = make_float2(sigm(zA1), sigm(zB1));
    *(float2*)(po + 2 * HW) = make_float2(sigm(zA2), sigm(zB2));
}

extern "C" void kernel_launch(void* const* d_in, const int* in_sizes, int n_in,
                              void* d_out, int out_size) {
    const float* x     = (const float*)d_in[0];
    const float* w_in  = (const float*)d_in[1];
    const float* ws    = (const float*)d_in[2];
    const float* w_out = (const float*)d_in[3];
    float* out = (float*)d_out;

    const int pairs = NB * HW / 2;            // 2,097,152
    dim3 block(128);
    dim3 grid(pairs / 128);                   // 16384
    simplenet_kernel<<<grid, block>>>(x, w_in, ws, w_out, out);
}

// round 6
// speedup vs baseline: 1.2094x; 1.1387x over previous
#include <cuda_runtime.h>
#include <cstdint>

#define HW   (1024 * 1024)
#define NB   4
#define NC   3
#define MH   25
#define NDEPTH 6
#define NOP  13           // neuron-pair count (25 outputs -> 13 pairs, last has pad)
#define NOPP 14           // padded to 14 for 16B-aligned rows

typedef unsigned long long u64;

// ---------- packed f32x2 helpers ----------
__device__ __forceinline__ u64 pack2(float lo, float hi) {
    u64 r; asm("mov.b64 %0, {%1, %2};" : "=l"(r) : "f"(lo), "f"(hi)); return r;
}
__device__ __forceinline__ void unpack2(u64 v, float& lo, float& hi) {
    asm("mov.b64 {%0, %1}, %2;" : "=f"(lo), "=f"(hi) : "l"(v));
}
__device__ __forceinline__ u64 fma2_(u64 a, u64 b, u64 c) {
    u64 d; asm("fma.rn.f32x2 %0, %1, %2, %3;" : "=l"(d) : "l"(a), "l"(b), "l"(c)); return d;
}
__device__ __forceinline__ u64 mul2_(u64 a, u64 b) {
    u64 d; asm("mul.rn.f32x2 %0, %1, %2;" : "=l"(d) : "l"(a), "l"(b)); return d;
}
__device__ __forceinline__ u64 add2_(u64 a, u64 b) {
    u64 d; asm("add.rn.f32x2 %0, %1, %2;" : "=l"(d) : "l"(a), "l"(b)); return d;
}
__device__ __forceinline__ u64 cpair(float c) {
    unsigned b = __float_as_uint(c);
    return ((u64)b << 32) | (u64)b;
}
__device__ __forceinline__ float ex2f(float a) {
    float r; asm("ex2.approx.f32 %0, %1;" : "=f"(r) : "f"(a)); return r;
}
__device__ __forceinline__ float rcpf(float a) {
    float r; asm("rcp.approx.f32 %0, %1;" : "=f"(r) : "f"(a)); return r;
}

struct TanhC {
    u64 c2log2e;   // {2*log2(e), 2*log2(e)}
    u64 one2;      // {1,1}
    u64 m22;       // {-2,-2}
};

// MUFU tanh: t = 1 - 2/(1 + 2^(2*log2e*x)).
// 3 packed fma-pipe ops + 4 MUFU lane-ops per pair; saturation handled
// naturally (ex2->inf, rcp(inf)=0 -> t=1; ex2->0 -> t=-1). No clamp.
__device__ __forceinline__ u64 tanh2(u64 v, const TanhC& K) {
    u64 f = mul2_(v, K.c2log2e);
    float fl, fh;
    unpack2(f, fl, fh);
    u64 e = pack2(ex2f(fl), ex2f(fh));
    u64 d = add2_(e, K.one2);
    float dl, dh;
    unpack2(d, dl, dh);
    u64 r = pack2(rcpf(dl), rcpf(dh));
    return fma2_(r, K.m22, K.one2);     // 1 - 2r
}

__device__ __forceinline__ float sigm(float z) {
    // 1/(1 + 2^(-z*log2e)) : 2 MUFU + 2 fma-pipe
    float e = ex2f(z * -1.44269504088896f);
    return rcpf(1.0f + e);
}

__global__ __launch_bounds__(128, 4)
void simplenet_kernel(const float* __restrict__ x,
                      const float* __restrict__ w_in,
                      const float* __restrict__ ws,
                      const float* __restrict__ w_out,
                      float* __restrict__ out) {
    // Weight layout: neuron-pair packing {w[2op][c], w[2op+1][c]} per u64.
    __shared__ __align__(16) u64   s_mid[NDEPTH][MH][NOPP];  // [layer][c][op]
    __shared__ __align__(16) u64   s_in[NC][NOPP];           // [c][op]
    __shared__ __align__(16) float s_wout[NOP][8];           // [i][o*2+half]

    const int tid = threadIdx.x;

    for (int t = tid; t < NDEPTH * MH * NOPP; t += 128) {
        int l  = t / (MH * NOPP);
        int r  = t - l * (MH * NOPP);
        int c  = r / NOPP;
        int op = r - c * NOPP;
        int o0 = 2 * op, o1 = 2 * op + 1;
        float lo = (o0 < MH) ? ws[(l * MH + o0) * MH + c] : 0.0f;
        float hi = (o1 < MH) ? ws[(l * MH + o1) * MH + c] : 0.0f;
        s_mid[l][c][op] = pack2(lo, hi);
    }
    for (int t = tid; t < NC * NOPP; t += 128) {
        int c = t / NOPP, op = t - (t / NOPP) * NOPP;
        int o0 = 2 * op, o1 = 2 * op + 1;
        float lo = (o0 < MH) ? w_in[o0 * NC + c] : 0.0f;
        float hi = (o1 < MH) ? w_in[o1 * NC + c] : 0.0f;
        s_in[c][op] = pack2(lo, hi);
    }
    for (int t = tid; t < NOP * 8; t += 128) {
        int i = t / 8, j = t - (t / 8) * 8;
        int o = j >> 1, half = j & 1;
        int c = 2 * i + half;
        s_wout[i][j] = (o < NC && c < MH) ? w_out[o * MH + c] : 0.0f;
    }
    __syncthreads();

    TanhC K;
    K.c2log2e = cpair(2.88539008177793f);   // 2*log2(e)
    K.one2    = cpair(1.0f);
    K.m22     = cpair(-2.0f);

    unsigned gp  = blockIdx.x * 128u + (unsigned)tid;   // pixel-pair index
    unsigned idx = gp * 2u;                             // grid covers domain exactly
    unsigned b   = idx >> 20;                 // / HW
    unsigned rem = idx & (HW - 1);

    const float* px = x + (size_t)b * (NC * HW) + rem;
    float2 v0 = *(const float2*)(px);                 // (pixA, pixB) channel 0
    float2 v1 = *(const float2*)(px + HW);
    float2 v2 = *(const float2*)(px + 2 * HW);

    // Per-pixel state: 13 neuron-pair accumulators each.
    u64 hA[NOP], hB[NOP];
    u64 aA[NOP], aB[NOP];

    // ---- input layer: 3 -> 25 (neuron-pair packed), tanh ----
    {
        u64 dA = pack2(v0.x, v0.x), dB = pack2(v0.y, v0.y);
#pragma unroll
        for (int op = 0; op < NOP; op++) {
            u64 w = s_in[0][op];
            aA[op] = mul2_(w, dA);
            aB[op] = mul2_(w, dB);
        }
        dA = pack2(v1.x, v1.x); dB = pack2(v1.y, v1.y);
#pragma unroll
        for (int op = 0; op < NOP; op++) {
            u64 w = s_in[1][op];
            aA[op] = fma2_(w, dA, aA[op]);
            aB[op] = fma2_(w, dB, aB[op]);
        }
        dA = pack2(v2.x, v2.x); dB = pack2(v2.y, v2.y);
#pragma unroll
        for (int op = 0; op < NOP; op++) {
            u64 w = s_in[2][op];
            aA[op] = fma2_(w, dA, aA[op]);
            aB[op] = fma2_(w, dB, aB[op]);
        }
#pragma unroll
        for (int op = 0; op < NOP; op++) {
            hA[op] = tanh2(aA[op], K);
            hB[op] = tanh2(aB[op], K);
        }
    }

    // ---- 6 hidden layers: 25 -> 25, tanh ----
#pragma unroll 1
    for (int l = 0; l < NDEPTH; l++) {
        const u64* wl = &s_mid[l][0][0];
#pragma unroll
        for (int i = 0; i < NOP; i++) {           // i indexes h pair (c = 2i, 2i+1)
            float a0, a1, b0, b1;
            unpack2(hA[i], a0, a1);
            unpack2(hB[i], b0, b1);
            {
                u64 dA = pack2(a0, a0), dB = pack2(b0, b0);
                const u64* wr = wl + (2 * i) * NOPP;
#pragma unroll
                for (int op = 0; op < NOP; op++) {
                    u64 w = wr[op];
                    if (i == 0) {
                        aA[op] = mul2_(w, dA);
                        aB[op] = mul2_(w, dB);
                    } else {
                        aA[op] = fma2_(w, dA, aA[op]);
                        aB[op] = fma2_(w, dB, aB[op]);
                    }
                }
            }
            if (2 * i + 1 < MH) {                 // skip pad lane c=25
                u64 dA = pack2(a1, a1), dB = pack2(b1, b1);
                const u64* wr = wl + (2 * i + 1) * NOPP;
#pragma unroll
                for (int op = 0; op < NOP; op++) {
                    u64 w = wr[op];
                    aA[op] = fma2_(w, dA, aA[op]);
                    aB[op] = fma2_(w, dB, aB[op]);
                }
            }
        }
#pragma unroll
        for (int op = 0; op < NOP; op++) {
            hA[op] = tanh2(aA[op], K);            // pad lane: tanh(0)=0
            hB[op] = tanh2(aB[op], K);
        }
    }

    // ---- output layer: 25 -> 3, scalar ----
    float zA0 = 0.f, zA1 = 0.f, zA2 = 0.f;
    float zB0 = 0.f, zB1 = 0.f, zB2 = 0.f;
#pragma unroll
    for (int i = 0; i < NOP; i++) {
        float a0, a1, b0, b1;
        unpack2(hA[i], a0, a1);
        unpack2(hB[i], b0, b1);
        float w00 = s_wout[i][0], w01 = s_wout[i][1];
        float w10 = s_wout[i][2], w11 = s_wout[i][3];
        float w20 = s_wout[i][4], w21 = s_wout[i][5];
        zA0 = fmaf(w00, a0, fmaf(w01, a1, zA0));
        zA1 = fmaf(w10, a0, fmaf(w11, a1, zA1));
        zA2 = fmaf(w20, a0, fmaf(w21, a1, zA2));
        zB0 = fmaf(w00, b0, fmaf(w01, b1, zB0));
        zB1 = fmaf(w10, b0, fmaf(w11, b1, zB1));
        zB2 = fmaf(w20, b0, fmaf(w21, b1, zB2));
    }

    float* po = out + (size_t)b * (NC * HW) + rem;
    *(float2*)(po)          = make_float2(sigm(zA0), sigm(zB0));
    *(float2*)(po + HW)     = make_float2(sigm(zA1), sigm(zB1));
    *(float2*)(po + 2 * HW) = make_float2(sigm(zA2), sigm(zB2));
}

extern "C" void kernel_launch(void* const* d_in, const int* in_sizes, int n_in,
                              void* d_out, int out_size) {
    const float* x     = (const float*)d_in[0];
    const float* w_in  = (const float*)d_in[1];
    const float* ws    = (const float*)d_in[2];
    const float* w_out = (const float*)d_in[3];
    float* out = (float*)d_out;

    const int pairs = NB * HW / 2;            // 2,097,152
    dim3 block(128);
    dim3 grid(pairs / 128);                   // 16384
    simplenet_kernel<<<grid, block>>>(x, w_in, ws, w_out, out);
}

// round 8
// speedup vs baseline: 1.2288x; 1.0161x over previous
#include <cuda_runtime.h>
#include <cstdint>

#define HW   (1024 * 1024)
#define NB   4
#define NC   3
#define MH   25
#define NDEPTH 6
#define NOP  13           // neuron-pair count (25 outputs -> 13 pairs, last has pad)
#define NOPP 14           // padded to 14 for 16B-aligned rows

typedef unsigned long long u64;

#define C2LOG2E 2.885390081777926815f    // 2*log2(e), folded into tanh-feeding weights
#define MLOG2E  (-1.442695040888963407f) // -log2(e), folded into w_out for sigmoid

// ---------- packed f32x2 helpers ----------
__device__ __forceinline__ u64 pack2(float lo, float hi) {
    u64 r; asm("mov.b64 %0, {%1, %2};" : "=l"(r) : "f"(lo), "f"(hi)); return r;
}
__device__ __forceinline__ void unpack2(u64 v, float& lo, float& hi) {
    asm("mov.b64 {%0, %1}, %2;" : "=f"(lo), "=f"(hi) : "l"(v));
}
__device__ __forceinline__ u64 fma2_(u64 a, u64 b, u64 c) {
    u64 d; asm("fma.rn.f32x2 %0, %1, %2, %3;" : "=l"(d) : "l"(a), "l"(b), "l"(c)); return d;
}
__device__ __forceinline__ u64 mul2_(u64 a, u64 b) {
    u64 d; asm("mul.rn.f32x2 %0, %1, %2;" : "=l"(d) : "l"(a), "l"(b)); return d;
}
__device__ __forceinline__ u64 add2_(u64 a, u64 b) {
    u64 d; asm("add.rn.f32x2 %0, %1, %2;" : "=l"(d) : "l"(a), "l"(b)); return d;
}
__device__ __forceinline__ u64 cpair(float c) {
    unsigned b = __float_as_uint(c);
    return ((u64)b << 32) | (u64)b;
}
__device__ __forceinline__ float ex2f(float a) {
    float r; asm("ex2.approx.f32 %0, %1;" : "=f"(r) : "f"(a)); return r;
}
__device__ __forceinline__ float rcpf(float a) {
    float r; asm("rcp.approx.f32 %0, %1;" : "=f"(r) : "f"(a)); return r;
}

struct TanhC {
    u64 one2;      // {1,1}
    u64 m22;       // {-2,-2}
};

// MUFU tanh on PRE-SCALED input zs = 2*log2(e)*z (scale folded into weights):
// t = 1 - 2/(1 + 2^zs). 2 packed fma-pipe ops + 4 MUFU lane-ops per pair.
// Saturation handled naturally (ex2->inf, rcp(inf)=0 -> t=1; ex2->0 -> t=-1).
__device__ __forceinline__ u64 tanh2s(u64 zs, const TanhC& K) {
    float fl, fh;
    unpack2(zs, fl, fh);
    u64 e = pack2(ex2f(fl), ex2f(fh));
    u64 d = add2_(e, K.one2);
    float dl, dh;
    unpack2(d, dl, dh);
    u64 r = pack2(rcpf(dl), rcpf(dh));
    return fma2_(r, K.m22, K.one2);     // 1 - 2r
}

// sigmoid on PRE-SCALED input zs = -log2(e)*z: 1/(1 + 2^zs)
__device__ __forceinline__ float sigms(float zs) {
    return rcpf(1.0f + ex2f(zs));
}

__global__ __launch_bounds__(128, 4)
void simplenet_kernel(const float* __restrict__ x,
                      const float* __restrict__ w_in,
                      const float* __restrict__ ws,
                      const float* __restrict__ w_out,
                      float* __restrict__ out) {
    // Weight layout: neuron-pair packing {w[2op][c], w[2op+1][c]} per u64,
    // pre-scaled by 2*log2(e) (tanh fold). Rows 16B-aligned for LDS.128.
    __shared__ __align__(16) u64   s_mid[NDEPTH][MH][NOPP];  // [layer][c][op]
    __shared__ __align__(16) u64   s_in[NC][NOPP];           // [c][op]
    __shared__ __align__(16) float s_wout[NOP][8];           // [i][o*2+half], scaled -log2e

    const int tid = threadIdx.x;

    for (int t = tid; t < NDEPTH * MH * NOPP; t += 128) {
        int l  = t / (MH * NOPP);
        int r  = t - l * (MH * NOPP);
        int c  = r / NOPP;
        int op = r - c * NOPP;
        int o0 = 2 * op, o1 = 2 * op + 1;
        float lo = (o0 < MH) ? ws[(l * MH + o0) * MH + c] * C2LOG2E : 0.0f;
        float hi = (o1 < MH) ? ws[(l * MH + o1) * MH + c] * C2LOG2E : 0.0f;
        s_mid[l][c][op] = pack2(lo, hi);
    }
    for (int t = tid; t < NC * NOPP; t += 128) {
        int c = t / NOPP, op = t - (t / NOPP) * NOPP;
        int o0 = 2 * op, o1 = 2 * op + 1;
        float lo = (o0 < MH) ? w_in[o0 * NC + c] * C2LOG2E : 0.0f;
        float hi = (o1 < MH) ? w_in[o1 * NC + c] * C2LOG2E : 0.0f;
        s_in[c][op] = pack2(lo, hi);
    }
    for (int t = tid; t < NOP * 8; t += 128) {
        int i = t / 8, j = t - (t / 8) * 8;
        int o = j >> 1, half = j & 1;
        int c = 2 * i + half;
        s_wout[i][j] = (o < NC && c < MH) ? w_out[o * MH + c] * MLOG2E : 0.0f;
    }
    __syncthreads();

    TanhC K;
    K.one2 = cpair(1.0f);
    K.m22  = cpair(-2.0f);

    unsigned gp  = blockIdx.x * 128u + (unsigned)tid;   // pixel-pair index
    unsigned idx = gp * 2u;                             // grid covers domain exactly
    unsigned b   = idx >> 20;                 // / HW
    unsigned rem = idx & (HW - 1);

    const float* px = x + (size_t)b * (NC * HW) + rem;
    float2 v0 = *(const float2*)(px);                 // (pixA, pixB) channel 0
    float2 v1 = *(const float2*)(px + HW);
    float2 v2 = *(const float2*)(px + 2 * HW);

    // Per-pixel state: 13 neuron-pair accumulators each.
    u64 hA[NOP], hB[NOP];
    u64 aA[NOP], aB[NOP];

    // ---- input layer: 3 -> 25 (neuron-pair packed, pre-scaled), tanh ----
    {
        u64 dA = pack2(v0.x, v0.x), dB = pack2(v0.y, v0.y);
#pragma unroll
        for (int op = 0; op < NOP; op++) {
            u64 w = s_in[0][op];
            aA[op] = mul2_(w, dA);
            aB[op] = mul2_(w, dB);
        }
        dA = pack2(v1.x, v1.x); dB = pack2(v1.y, v1.y);
#pragma unroll
        for (int op = 0; op < NOP; op++) {
            u64 w = s_in[1][op];
            aA[op] = fma2_(w, dA, aA[op]);
            aB[op] = fma2_(w, dB, aB[op]);
        }
        dA = pack2(v2.x, v2.x); dB = pack2(v2.y, v2.y);
#pragma unroll
        for (int op = 0; op < NOP; op++) {
            u64 w = s_in[2][op];
            aA[op] = fma2_(w, dA, aA[op]);
            aB[op] = fma2_(w, dB, aB[op]);
        }
#pragma unroll
        for (int op = 0; op < NOP; op++) {
            hA[op] = tanh2s(aA[op], K);
            hB[op] = tanh2s(aB[op], K);
        }
    }

    // ---- 6 hidden layers: 25 -> 25, tanh ----
#pragma unroll 1
    for (int l = 0; l < NDEPTH; l++) {
        const u64* wl = &s_mid[l][0][0];
#pragma unroll
        for (int i = 0; i < NOP; i++) {           // i indexes h pair (c = 2i, 2i+1)
            float a0, a1, b0, b1;
            unpack2(hA[i], a0, a1);
            unpack2(hB[i], b0, b1);
            {
                u64 dA = pack2(a0, a0), dB = pack2(b0, b0);
                const ulonglong2* wr2 = (const ulonglong2*)(wl + (2 * i) * NOPP);
#pragma unroll
                for (int q = 0; q < 6; q++) {     // ops 0..11 via LDS.128
                    ulonglong2 w2 = wr2[q];
                    if (i == 0) {                 // first contribution: init ALL accumulators
                        aA[2 * q]     = mul2_(w2.x, dA);
                        aB[2 * q]     = mul2_(w2.x, dB);
                        aA[2 * q + 1] = mul2_(w2.y, dA);
                        aB[2 * q + 1] = mul2_(w2.y, dB);
                    } else {
                        aA[2 * q]     = fma2_(w2.x, dA, aA[2 * q]);
                        aB[2 * q]     = fma2_(w2.x, dB, aB[2 * q]);
                        aA[2 * q + 1] = fma2_(w2.y, dA, aA[2 * q + 1]);
                        aB[2 * q + 1] = fma2_(w2.y, dB, aB[2 * q + 1]);
                    }
                }
                ulonglong2 w2 = wr2[6];           // op 12 (+pad)
                if (i == 0) {
                    aA[12] = mul2_(w2.x, dA);
                    aB[12] = mul2_(w2.x, dB);
                } else {
                    aA[12] = fma2_(w2.x, dA, aA[12]);
                    aB[12] = fma2_(w2.x, dB, aB[12]);
                }
            }
            if (2 * i + 1 < MH) {                 // skip pad lane c=25
                u64 dA = pack2(a1, a1), dB = pack2(b1, b1);
                const ulonglong2* wr2 = (const ulonglong2*)(wl + (2 * i + 1) * NOPP);
#pragma unroll
                for (int q = 0; q < 6; q++) {
                    ulonglong2 w2 = wr2[q];
                    aA[2 * q]     = fma2_(w2.x, dA, aA[2 * q]);
                    aB[2 * q]     = fma2_(w2.x, dB, aB[2 * q]);
                    aA[2 * q + 1] = fma2_(w2.y, dA, aA[2 * q + 1]);
                    aB[2 * q + 1] = fma2_(w2.y, dB, aB[2 * q + 1]);
                }
                ulonglong2 w2 = wr2[6];
                aA[12] = fma2_(w2.x, dA, aA[12]);
                aB[12] = fma2_(w2.x, dB, aB[12]);
            }
        }
#pragma unroll
        for (int op = 0; op < NOP; op++) {
            hA[op] = tanh2s(aA[op], K);           // pad lane: tanh(0)=0
            hB[op] = tanh2s(aB[op], K);
        }
    }

    // ---- output layer: 25 -> 3 (weights pre-scaled by -log2e), sigmoid ----
    float zA0 = 0.f, zA1 = 0.f, zA2 = 0.f;
    float zB0 = 0.f, zB1 = 0.f, zB2 = 0.f;
#pragma unroll
    for (int i = 0; i < NOP; i++) {
        float a0, a1, b0, b1;
        unpack2(hA[i], a0, a1);
        unpack2(hB[i], b0, b1);
        float w00 = s_wout[i][0], w01 = s_wout[i][1];
        float w10 = s_wout[i][2], w11 = s_wout[i][3];
        float w20 = s_wout[i][4], w21 = s_wout[i][5];
        zA0 = fmaf(w00, a0, fmaf(w01, a1, zA0));
        zA1 = fmaf(w10, a0, fmaf(w11, a1, zA1));
        zA2 = fmaf(w20, a0, fmaf(w21, a1, zA2));
        zB0 = fmaf(w00, b0, fmaf(w01, b1, zB0));
        zB1 = fmaf(w10, b0, fmaf(w11, b1, zB1));
        zB2 = fmaf(w20, b0, fmaf(w21, b1, zB2));
    }

    float* po = out + (size_t)b * (NC * HW) + rem;
    *(float2*)(po)          = make_float2(sigms(zA0), sigms(zB0));
    *(float2*)(po + HW)     = make_float2(sigms(zA1), sigms(zB1));
    *(float2*)(po + 2 * HW) = make_float2(sigms(zA2), sigms(zB2));
}

extern "C" void kernel_launch(void* const* d_in, const int* in_sizes, int n_in,
                              void* d_out, int out_size) {
    const float* x     = (const float*)d_in[0];
    const float* w_in  = (const float*)d_in[1];
    const float* ws    = (const float*)d_in[2];
    const float* w_out = (const float*)d_in[3];
    float* out = (float*)d_out;

    const int pairs = NB * HW / 2;            // 2,097,152
    dim3 block(128);
    dim3 grid(pairs / 128);                   // 16384
    simplenet_kernel<<<grid, block>>>(x, w_in, ws, w_out, out);
}

// round 9
// speedup vs baseline: 1.2431x; 1.0116x over previous
#include <cuda_runtime.h>
#include <cstdint>

#define HW   (1024 * 1024)
#define NB   4
#define NC   3
#define MH   25
#define NDEPTH 6
#define NOP  13           // neuron-pair count (25 outputs -> 13 pairs, last has pad)
#define NOPP 14           // padded to 14 for 16B-aligned rows

typedef unsigned long long u64;

#define C2LOG2E 2.885390081777926815f    // 2*log2(e), folded into tanh-feeding weights
#define MLOG2E  (-1.442695040888963407f) // -log2(e), folded into w_out for sigmoid

// ---------- packed f32x2 helpers ----------
__device__ __forceinline__ u64 pack2(float lo, float hi) {
    u64 r; asm("mov.b64 %0, {%1, %2};" : "=l"(r) : "f"(lo), "f"(hi)); return r;
}
__device__ __forceinline__ void unpack2(u64 v, float& lo, float& hi) {
    asm("mov.b64 {%0, %1}, %2;" : "=f"(lo), "=f"(hi) : "l"(v));
}
__device__ __forceinline__ u64 fma2_(u64 a, u64 b, u64 c) {
    u64 d; asm("fma.rn.f32x2 %0, %1, %2, %3;" : "=l"(d) : "l"(a), "l"(b), "l"(c)); return d;
}
__device__ __forceinline__ u64 mul2_(u64 a, u64 b) {
    u64 d; asm("mul.rn.f32x2 %0, %1, %2;" : "=l"(d) : "l"(a), "l"(b)); return d;
}
__device__ __forceinline__ u64 add2_(u64 a, u64 b) {
    u64 d; asm("add.rn.f32x2 %0, %1, %2;" : "=l"(d) : "l"(a), "l"(b)); return d;
}
__device__ __forceinline__ u64 cpair(float c) {
    unsigned b = __float_as_uint(c);
    return ((u64)b << 32) | (u64)b;
}
__device__ __forceinline__ float ex2f(float a) {
    float r; asm("ex2.approx.f32 %0, %1;" : "=f"(r) : "f"(a)); return r;
}
__device__ __forceinline__ float rcpf(float a) {
    float r; asm("rcp.approx.f32 %0, %1;" : "=f"(r) : "f"(a)); return r;
}

struct TanhC {
    u64 one2;      // {1,1}
    u64 m22;       // {-2,-2}
};

// MUFU tanh on PRE-SCALED input zs = 2*log2(e)*z (scale folded into weights):
// t = 1 - 2/(1 + 2^zs). 2 packed fma-pipe ops + 4 MUFU lane-ops per pair.
__device__ __forceinline__ u64 tanh2s(u64 zs, const TanhC& K) {
    float fl, fh;
    unpack2(zs, fl, fh);
    u64 e = pack2(ex2f(fl), ex2f(fh));
    u64 d = add2_(e, K.one2);
    float dl, dh;
    unpack2(d, dl, dh);
    u64 r = pack2(rcpf(dl), rcpf(dh));
    return fma2_(r, K.m22, K.one2);     // 1 - 2r
}

// sigmoid on PRE-SCALED input zs = -log2(e)*z: 1/(1 + 2^zs)
__device__ __forceinline__ float sigms(float zs) {
    return rcpf(1.0f + ex2f(zs));
}

// 25->25 matmul for one pixel-pair (A,B): weights neuron-pair packed.
__device__ __forceinline__ void mm_hidden(const u64* __restrict__ wl,
                                          const u64* hA, const u64* hB,
                                          u64* aA, u64* aB) {
#pragma unroll
    for (int i = 0; i < NOP; i++) {           // i indexes h pair (c = 2i, 2i+1)
        float a0, a1, b0, b1;
        unpack2(hA[i], a0, a1);
        unpack2(hB[i], b0, b1);
        {
            u64 dA = pack2(a0, a0), dB = pack2(b0, b0);
            const ulonglong2* wr2 = (const ulonglong2*)(wl + (2 * i) * NOPP);
#pragma unroll
            for (int q = 0; q < 6; q++) {
                ulonglong2 w2 = wr2[q];
                if (i == 0) {
                    aA[2 * q]     = mul2_(w2.x, dA);
                    aB[2 * q]     = mul2_(w2.x, dB);
                    aA[2 * q + 1] = mul2_(w2.y, dA);
                    aB[2 * q + 1] = mul2_(w2.y, dB);
                } else {
                    aA[2 * q]     = fma2_(w2.x, dA, aA[2 * q]);
                    aB[2 * q]     = fma2_(w2.x, dB, aB[2 * q]);
                    aA[2 * q + 1] = fma2_(w2.y, dA, aA[2 * q + 1]);
                    aB[2 * q + 1] = fma2_(w2.y, dB, aB[2 * q + 1]);
                }
            }
            ulonglong2 w2 = wr2[6];           // op 12 (+pad)
            if (i == 0) {
                aA[12] = mul2_(w2.x, dA);
                aB[12] = mul2_(w2.x, dB);
            } else {
                aA[12] = fma2_(w2.x, dA, aA[12]);
                aB[12] = fma2_(w2.x, dB, aB[12]);
            }
        }
        if (2 * i + 1 < MH) {                 // skip pad lane c=25
            u64 dA = pack2(a1, a1), dB = pack2(b1, b1);
            const ulonglong2* wr2 = (const ulonglong2*)(wl + (2 * i + 1) * NOPP);
#pragma unroll
            for (int q = 0; q < 6; q++) {
                ulonglong2 w2 = wr2[q];
                aA[2 * q]     = fma2_(w2.x, dA, aA[2 * q]);
                aB[2 * q]     = fma2_(w2.x, dB, aB[2 * q]);
                aA[2 * q + 1] = fma2_(w2.y, dA, aA[2 * q + 1]);
                aB[2 * q + 1] = fma2_(w2.y, dB, aB[2 * q + 1]);
            }
            ulonglong2 w2 = wr2[6];
            aA[12] = fma2_(w2.x, dA, aA[12]);
            aB[12] = fma2_(w2.x, dB, aB[12]);
        }
    }
}

__device__ __forceinline__ void tanh_set(const u64* aA, const u64* aB,
                                         u64* hA, u64* hB, const TanhC& K) {
#pragma unroll
    for (int op = 0; op < NOP; op++) {
        hA[op] = tanh2s(aA[op], K);
        hB[op] = tanh2s(aB[op], K);
    }
}

// input layer 3->25 for one pixel-pair
__device__ __forceinline__ void mm_input(const u64 (*s_in)[NOPP],
                                         float pA0, float pB0, float pA1, float pB1,
                                         float pA2, float pB2,
                                         u64* aA, u64* aB) {
    u64 dA = pack2(pA0, pA0), dB = pack2(pB0, pB0);
#pragma unroll
    for (int op = 0; op < NOP; op++) {
        u64 w = s_in[0][op];
        aA[op] = mul2_(w, dA);
        aB[op] = mul2_(w, dB);
    }
    dA = pack2(pA1, pA1); dB = pack2(pB1, pB1);
#pragma unroll
    for (int op = 0; op < NOP; op++) {
        u64 w = s_in[1][op];
        aA[op] = fma2_(w, dA, aA[op]);
        aB[op] = fma2_(w, dB, aB[op]);
    }
    dA = pack2(pA2, pA2); dB = pack2(pB2, pB2);
#pragma unroll
    for (int op = 0; op < NOP; op++) {
        u64 w = s_in[2][op];
        aA[op] = fma2_(w, dA, aA[op]);
        aB[op] = fma2_(w, dB, aB[op]);
    }
}

__global__ __launch_bounds__(256, 1)
void simplenet_kernel(const float* __restrict__ x,
                      const float* __restrict__ w_in,
                      const float* __restrict__ ws,
                      const float* __restrict__ w_out,
                      float* __restrict__ out) {
    __shared__ __align__(16) u64   s_mid[NDEPTH][MH][NOPP];  // [layer][c][op], scaled 2log2e
    __shared__ __align__(16) u64   s_in[NC][NOPP];           // [c][op], scaled 2log2e
    __shared__ __align__(16) float s_wout[NOP][8];           // [i][o*2+half], scaled -log2e

    const int tid = threadIdx.x;

    for (int t = tid; t < NDEPTH * MH * NOPP; t += 256) {
        int l  = t / (MH * NOPP);
        int r  = t - l * (MH * NOPP);
        int c  = r / NOPP;
        int op = r - c * NOPP;
        int o0 = 2 * op, o1 = 2 * op + 1;
        float lo = (o0 < MH) ? ws[(l * MH + o0) * MH + c] * C2LOG2E : 0.0f;
        float hi = (o1 < MH) ? ws[(l * MH + o1) * MH + c] * C2LOG2E : 0.0f;
        s_mid[l][c][op] = pack2(lo, hi);
    }
    for (int t = tid; t < NC * NOPP; t += 256) {
        int c = t / NOPP, op = t - (t / NOPP) * NOPP;
        int o0 = 2 * op, o1 = 2 * op + 1;
        float lo = (o0 < MH) ? w_in[o0 * NC + c] * C2LOG2E : 0.0f;
        float hi = (o1 < MH) ? w_in[o1 * NC + c] * C2LOG2E : 0.0f;
        s_in[c][op] = pack2(lo, hi);
    }
    for (int t = tid; t < NOP * 8; t += 256) {
        int i = t / 8, j = t - (t / 8) * 8;
        int o = j >> 1, half = j & 1;
        int c = 2 * i + half;
        s_wout[i][j] = (o < NC && c < MH) ? w_out[o * MH + c] * MLOG2E : 0.0f;
    }
    __syncthreads();

    TanhC K;
    K.one2 = cpair(1.0f);
    K.m22  = cpair(-2.0f);

    // 4 pixels per thread: pair-set P = (A,B), Q = (C,D)
    unsigned gp4 = (blockIdx.x * 256u + (unsigned)tid) * 4u;
    unsigned b   = gp4 >> 20;
    unsigned rem = gp4 & (HW - 1);

    const float* px = x + (size_t)b * (NC * HW) + rem;
    float4 c0 = *(const float4*)(px);
    float4 c1 = *(const float4*)(px + HW);
    float4 c2 = *(const float4*)(px + 2 * HW);

    u64 hA[NOP], hB[NOP], hC[NOP], hD[NOP];
    u64 aA[NOP], aB[NOP], aC[NOP], aD[NOP];

    // prologue: input layer both sets, tanh(P)
    mm_input(s_in, c0.x, c0.y, c1.x, c1.y, c2.x, c2.y, aA, aB);
    mm_input(s_in, c0.z, c0.w, c1.z, c1.w, c2.z, c2.w, aC, aD);
    tanh_set(aA, aB, hA, hB, K);

    // rotated pipeline: tanh(Q, l-1) overlaps mm(P, l); tanh(P, l) overlaps mm(Q, l)
#pragma unroll 1
    for (int l = 0; l < NDEPTH; l++) {
        const u64* wl = &s_mid[l][0][0];
        tanh_set(aC, aD, hC, hD, K);          // tanh(Q, l-1) — independent of mm(P, l)
        mm_hidden(wl, hA, hB, aA, aB);        // mm(P, l)
        mm_hidden(wl, hC, hD, aC, aD);        // mm(Q, l)
        tanh_set(aA, aB, hA, hB, K);          // tanh(P, l) — independent of mm(Q, l)
    }
    tanh_set(aC, aD, hC, hD, K);              // tanh(Q, 5)

    // ---- output layer: 25 -> 3 for 4 pixels (weights pre-scaled -log2e) ----
    float zA0 = 0.f, zA1 = 0.f, zA2 = 0.f;
    float zB0 = 0.f, zB1 = 0.f, zB2 = 0.f;
    float zC0 = 0.f, zC1 = 0.f, zC2 = 0.f;
    float zD0 = 0.f, zD1 = 0.f, zD2 = 0.f;
#pragma unroll
    for (int i = 0; i < NOP; i++) {
        float a0, a1, b0, b1, cc0, cc1, d0, d1;
        unpack2(hA[i], a0, a1);
        unpack2(hB[i], b0, b1);
        unpack2(hC[i], cc0, cc1);
        unpack2(hD[i], d0, d1);
        float w00 = s_wout[i][0], w01 = s_wout[i][1];
        float w10 = s_wout[i][2], w11 = s_wout[i][3];
        float w20 = s_wout[i][4], w21 = s_wout[i][5];
        zA0 = fmaf(w00, a0, fmaf(w01, a1, zA0));
        zA1 = fmaf(w10, a0, fmaf(w11, a1, zA1));
        zA2 = fmaf(w20, a0, fmaf(w21, a1, zA2));
        zB0 = fmaf(w00, b0, fmaf(w01, b1, zB0));
        zB1 = fmaf(w10, b0, fmaf(w11, b1, zB1));
        zB2 = fmaf(w20, b0, fmaf(w21, b1, zB2));
        zC0 = fmaf(w00, cc0, fmaf(w01, cc1, zC0));
        zC1 = fmaf(w10, cc0, fmaf(w11, cc1, zC1));
        zC2 = fmaf(w20, cc0, fmaf(w21, cc1, zC2));
        zD0 = fmaf(w00, d0, fmaf(w01, d1, zD0));
        zD1 = fmaf(w10, d0, fmaf(w11, d1, zD1));
        zD2 = fmaf(w20, d0, fmaf(w21, d1, zD2));
    }

    float* po = out + (size_t)b * (NC * HW) + rem;
    *(float4*)(po)          = make_float4(sigms(zA0), sigms(zB0), sigms(zC0), sigms(zD0));
    *(float4*)(po + HW)     = make_float4(sigms(zA1), sigms(zB1), sigms(zC1), sigms(zD1));
    *(float4*)(po + 2 * HW) = make_float4(sigms(zA2), sigms(zB2), sigms(zC2), sigms(zD2));
}

extern "C" void kernel_launch(void* const* d_in, const int* in_sizes, int n_in,
                              void* d_out, int out_size) {
    const float* x     = (const float*)d_in[0];
    const float* w_in  = (const float*)d_in[1];
    const float* ws    = (const float*)d_in[2];
    const float* w_out = (const float*)d_in[3];
    float* out = (float*)d_out;

    const int quads = NB * HW / 4;            // 1,048,576
    dim3 block(256);
    dim3 grid(quads / 256);                   // 4096
    simplenet_kernel<<<grid, block>>>(x, w_in, ws, w_out, out);
}